// round 2
// baseline (speedup 1.0000x reference)
#include <cuda_runtime.h>
#include <cuda_bf16.h>
#include <cstddef>

#define E_TOT 512
#define Dd    64
#define Hh    256
#define Nn    16
#define Aa    8
#define Tt    128
#define RPB   8          // MLP rows per block
#define KT    16         // MLP weight k-tile

#define SF2   0.01f
#define SN2   0.01f
#define NEG_HALF_INV_L2 (-50.0f)   // -0.5 / 0.1^2

// scratch (no allocation allowed -> device globals)
__device__ float g_times[E_TOT * Nn];
__device__ float g_anchors[E_TOT * Aa * Nn];
__device__ float g_St[E_TOT * Nn * Tt];   // Ks transposed per e: [16][128]
__device__ float g_U [E_TOT * Tt * Nn];   // U = Ks K^-1 per e:  [128][16]

// ---------------------------------------------------------------------------
// Kernel 1: MLP. 64 blocks x 8 rows, 256 threads, weight tiles staged in smem
// (coalesced LDG, conflict-free LDS) -- fixes the 32-line-per-LDG stride issue.
// ---------------------------------------------------------------------------
__global__ __launch_bounds__(256)
void mlp_kernel(const float* __restrict__ x,
                const float* __restrict__ W1, const float* __restrict__ b1,
                const float* __restrict__ W2, const float* __restrict__ b2,
                const float* __restrict__ Wt, const float* __restrict__ bt,
                const float* __restrict__ Wa, const float* __restrict__ ba)
{
    __shared__ float xs[RPB][Dd + 4];
    __shared__ float h1[RPB][Hh + 4];
    __shared__ float h2[RPB][Hh + 4];
    __shared__ float Ws[Hh][KT + 4];      // 256 x 20 x 4B = 20 KB tile

    const int tid = threadIdx.x;
    const int e0  = blockIdx.x * RPB;

    for (int idx = tid; idx < RPB * Dd; idx += 256)
        xs[idx >> 6][idx & 63] = x[e0 * Dd + idx];

    // ---- layer 1: h1[r][tid] = tanh(dot(W1[tid,:], x[r,:]) + b1[tid]) ----
    {
        float acc[RPB];
        float bias = b1[tid];
        #pragma unroll
        for (int r = 0; r < RPB; r++) acc[r] = bias;
        for (int kt = 0; kt < Dd / KT; kt++) {
            __syncthreads();
            for (int idx = tid; idx < Hh * KT; idx += 256) {
                int row = idx >> 4, cc = idx & 15;
                Ws[row][cc] = W1[row * Dd + kt * KT + cc];
            }
            __syncthreads();
            #pragma unroll
            for (int cc = 0; cc < KT; cc += 4) {
                float4 w4 = *(const float4*)&Ws[tid][cc];
                #pragma unroll
                for (int r = 0; r < RPB; r++) {
                    float4 v4 = *(const float4*)&xs[r][kt * KT + cc];
                    acc[r] += w4.x * v4.x + w4.y * v4.y + w4.z * v4.z + w4.w * v4.w;
                }
            }
        }
        __syncthreads();
        #pragma unroll
        for (int r = 0; r < RPB; r++) h1[r][tid] = tanhf(acc[r]);
    }
    __syncthreads();

    // ---- layer 2 ----
    {
        float acc[RPB];
        float bias = b2[tid];
        #pragma unroll
        for (int r = 0; r < RPB; r++) acc[r] = bias;
        for (int kt = 0; kt < Hh / KT; kt++) {
            __syncthreads();
            for (int idx = tid; idx < Hh * KT; idx += 256) {
                int row = idx >> 4, cc = idx & 15;
                Ws[row][cc] = W2[row * Hh + kt * KT + cc];
            }
            __syncthreads();
            #pragma unroll
            for (int cc = 0; cc < KT; cc += 4) {
                float4 w4 = *(const float4*)&Ws[tid][cc];
                #pragma unroll
                for (int r = 0; r < RPB; r++) {
                    float4 v4 = *(const float4*)&h1[r][kt * KT + cc];
                    acc[r] += w4.x * v4.x + w4.y * v4.y + w4.z * v4.z + w4.w * v4.w;
                }
            }
        }
        __syncthreads();
        #pragma unroll
        for (int r = 0; r < RPB; r++) h2[r][tid] = tanhf(acc[r]);
    }
    __syncthreads();

    // ---- heads: 144 output rows (16 times + 128 anchors), no activation ----
    {
        const int HO = Nn + Aa * Nn;  // 144
        float acc[RPB];
        float bias = 0.0f;
        if (tid < Nn)      bias = bt[tid];
        else if (tid < HO) bias = ba[tid - Nn];
        #pragma unroll
        for (int r = 0; r < RPB; r++) acc[r] = bias;
        for (int kt = 0; kt < Hh / KT; kt++) {
            __syncthreads();
            for (int idx = tid; idx < HO * KT; idx += 256) {
                int row = idx >> 4, cc = idx & 15;
                const float* src = (row < Nn) ? (Wt + row * Hh) : (Wa + (row - Nn) * Hh);
                Ws[row][cc] = src[kt * KT + cc];
            }
            __syncthreads();
            if (tid < HO) {
                #pragma unroll
                for (int cc = 0; cc < KT; cc += 4) {
                    float4 w4 = *(const float4*)&Ws[tid][cc];
                    #pragma unroll
                    for (int r = 0; r < RPB; r++) {
                        float4 v4 = *(const float4*)&h2[r][kt * KT + cc];
                        acc[r] += w4.x * v4.x + w4.y * v4.y + w4.z * v4.z + w4.w * v4.w;
                    }
                }
            }
        }
        if (tid < Nn) {
            #pragma unroll
            for (int r = 0; r < RPB; r++) g_times[(e0 + r) * Nn + tid] = acc[r];
        } else if (tid < HO) {
            #pragma unroll
            for (int r = 0; r < RPB; r++) g_anchors[(e0 + r) * (Aa * Nn) + (tid - Nn)] = acc[r];
        }
    }
}

// ---------------------------------------------------------------------------
// Kernel 2 (GPA): per-e GP solve. Warp 0 does Gauss-Jordan (syncwarp only)
// while warps 1-7 compute Ks. Writes mu + U/St scratch.
// ---------------------------------------------------------------------------
__global__ __launch_bounds__(256)
void gpa_kernel(const float* __restrict__ tq_g, float* __restrict__ out_mu)
{
    __shared__ float tq[Tt];
    __shared__ float tt[Nn];
    __shared__ float ys[Aa][Nn];
    __shared__ float Aug[Nn][2 * Nn + 1];   // [K | I] -> [I | K^-1]
    __shared__ float St[Nn][Tt + 4];        // Ks transposed
    __shared__ float Us[Tt][Nn + 1];        // U = Ks K^-1

    const int e    = blockIdx.x;
    const int tid  = threadIdx.x;
    const int wid  = tid >> 5;
    const int lane = tid & 31;

    if (tid < Tt) {
        tq[tid] = tq_g[tid];
        ys[tid >> 4][tid & 15] = g_anchors[e * (Aa * Nn) + tid];
    } else if (tid < Tt + Nn) {
        tt[tid - Tt] = g_times[e * Nn + (tid - Tt)];
    }
    __syncthreads();

    if (wid == 0) {
        // build augmented [K + sn2 I | I]
        #pragma unroll
        for (int r = 0; r < 8; r++) {
            int idx = r * 32 + lane;
            int i = idx >> 4, j = idx & 15;
            float d = tt[i] - tt[j];
            float v = SF2 * __expf(NEG_HALF_INV_L2 * d * d);
            if (i == j) v += SN2;
            Aug[i][j] = v;
            Aug[i][Nn + j] = (i == j) ? 1.0f : 0.0f;
        }
        __syncwarp();
        // Gauss-Jordan, lane = column (32 augmented columns), SPD no pivoting
        for (int k = 0; k < Nn; k++) {
            float pinv = 1.0f / Aug[k][k];
            float rowk = Aug[k][lane] * pinv;
            Aug[k][lane] = rowk;
            __syncwarp();
            #pragma unroll
            for (int i = 0; i < Nn; i++) {
                if (i != k) {
                    float c = Aug[i][k];           // LDS before STS, same instr stream
                    Aug[i][lane] -= c * rowk;
                }
            }
            __syncwarp();
        }
    } else {
        // warps 1..7: Ks transposed
        for (int idx = tid - 32; idx < Tt * Nn; idx += 224) {
            int j = idx >> 4, n = idx & 15;
            float d = tq[j] - tt[n];
            St[n][j] = SF2 * __expf(NEG_HALF_INV_L2 * d * d);
        }
    }
    __syncthreads();

    // U[i][n] = sum_m Ks[i][m] * Kinv[m][n]
    for (int idx = tid; idx < Tt * Nn; idx += 256) {
        int i = idx >> 4, n = idx & 15;
        float s = 0.0f;
        #pragma unroll
        for (int m = 0; m < Nn; m++) s += St[m][i] * Aug[m][Nn + n];
        Us[i][n] = s;
    }
    __syncthreads();

    // mu[a][i] = dot(U[i], y[a])
    for (int idx = tid; idx < Aa * Tt; idx += 256) {
        int a = idx >> 7, i = idx & 127;
        float s = 0.0f;
        #pragma unroll
        for (int n = 0; n < Nn; n++) s += Us[i][n] * ys[a][n];
        out_mu[((size_t)e * Aa + a) * Tt + i] = s;
    }

    // scratch out (coalesced)
    for (int idx = tid; idx < Tt * Nn; idx += 256)
        g_St[e * (Tt * Nn) + idx] = St[idx >> 7][idx & 127];
    for (int idx = tid; idx < Tt * Nn; idx += 256)
        g_U[e * (Tt * Nn) + idx] = Us[idx >> 4][idx & 15];
}

// ---------------------------------------------------------------------------
// Kernel 3 (GPB): pure cov store machine. 2048 blocks (e x 4 chunks of 32 i),
// reads ~10KB/block from L2, writes 128KB/block with coalesced STG.128.
// ---------------------------------------------------------------------------
__global__ __launch_bounds__(256)
void gpb_kernel(const float* __restrict__ tq_g, float* __restrict__ out_cov)
{
    __shared__ float tq[Tt];
    __shared__ float kssd[Tt];              // Kss[i][j] == kssd[|i-j|]
    __shared__ float St[Nn][Tt + 4];
    __shared__ float Us[32][Nn + 1];

    const int b   = blockIdx.x;
    const int e   = b >> 2;
    const int c   = b & 3;                  // i-chunk
    const int tid = threadIdx.x;

    if (tid < Tt) tq[tid] = tq_g[tid];
    __syncthreads();
    if (tid < Tt) {
        float d = tq[tid] - tq[0];
        kssd[tid] = SF2 * __expf(NEG_HALF_INV_L2 * d * d);
    }
    for (int idx = tid; idx < Tt * Nn; idx += 256)
        St[idx >> 7][idx & 127] = g_St[e * (Tt * Nn) + idx];
    for (int idx = tid; idx < 32 * Nn; idx += 256)
        Us[idx >> 4][idx & 15] = g_U[e * (Tt * Nn) + c * (32 * Nn) + idx];
    __syncthreads();

    const int lane = tid & 31;
    const int grp  = tid >> 5;
    const int j0   = lane * 4;
    #pragma unroll
    for (int step = 0; step < 4; step++) {
        int il = step * 8 + grp;            // 0..31 within chunk
        int i  = c * 32 + il;
        float u[Nn];
        #pragma unroll
        for (int n = 0; n < Nn; n++) u[n] = Us[il][n];   // broadcast LDS
        float a0 = 0.f, a1 = 0.f, a2 = 0.f, a3 = 0.f;
        #pragma unroll
        for (int n = 0; n < Nn; n++) {
            float4 s4 = *(const float4*)&St[n][j0];      // conflict-free LDS.128
            float un = u[n];
            a0 += un * s4.x; a1 += un * s4.y; a2 += un * s4.z; a3 += un * s4.w;
        }
        int d0 = i - j0;       d0 = d0 < 0 ? -d0 : d0;
        int d1 = i - (j0 + 1); d1 = d1 < 0 ? -d1 : d1;
        int d2 = i - (j0 + 2); d2 = d2 < 0 ? -d2 : d2;
        int d3 = i - (j0 + 3); d3 = d3 < 0 ? -d3 : d3;
        float4 v;
        v.x = kssd[d0] - a0;
        v.y = kssd[d1] - a1;
        v.z = kssd[d2] - a2;
        v.w = kssd[d3] - a3;
        size_t base = (((size_t)e * Aa) * Tt + i) * Tt + j0;
        #pragma unroll
        for (int a = 0; a < Aa; a++)
            *(float4*)&out_cov[base + (size_t)a * Tt * Tt] = v;   // coalesced STG.128
    }
}

// ---------------------------------------------------------------------------
extern "C" void kernel_launch(void* const* d_in, const int* in_sizes, int n_in,
                              void* d_out, int out_size)
{
    const float* x  = (const float*)d_in[0];
    // d_in[1] = a, d_in[2] = da (unused by reference)
    const float* W1 = (const float*)d_in[3];
    const float* b1 = (const float*)d_in[4];
    const float* W2 = (const float*)d_in[5];
    const float* b2 = (const float*)d_in[6];
    const float* Wt = (const float*)d_in[7];
    const float* bt = (const float*)d_in[8];
    const float* Wa = (const float*)d_in[9];
    const float* ba = (const float*)d_in[10];
    const float* tq = (const float*)d_in[11];

    float* out     = (float*)d_out;
    float* out_mu  = out;                                   // E*A*T floats
    float* out_cov = out + (size_t)E_TOT * Aa * Tt;         // E*A*T*T floats

    mlp_kernel<<<E_TOT / RPB, 256>>>(x, W1, b1, W2, b2, Wt, bt, Wa, ba);
    gpa_kernel<<<E_TOT, 256>>>(tq, out_mu);
    gpb_kernel<<<E_TOT * 4, 256>>>(tq, out_cov);
}

// round 3
// speedup vs baseline: 1.2991x; 1.2991x over previous
#include <cuda_runtime.h>
#include <cuda_bf16.h>
#include <cstddef>

#define E_TOT 512
#define Dd    64
#define Hh    256
#define Nn    16
#define Aa    8
#define Tt    128
#define RPB   4          // MLP rows per block -> 128 blocks
#define HO    (Nn + Aa * Nn)   // 144 head outputs

#define SF2   0.01f
#define SN2   0.01f
#define NEG_HALF_INV_L2 (-50.0f)   // -0.5 / 0.1^2

// scratch (no allocation allowed -> device globals)
__device__ float g_times[E_TOT * Nn];
__device__ float g_anchors[E_TOT * Aa * Nn];
__device__ float g_WT1[Dd * Hh];    // W1^T : [64][256]
__device__ float g_WT2[Hh * Hh];    // W2^T : [256][256]
__device__ float g_WhT[Hh * HO];    // [Wt;Wa]^T : [256][144]

// ---------------------------------------------------------------------------
// Kernel 0: transpose weights into column-major scratch (tiny, ~119K elems)
// ---------------------------------------------------------------------------
__global__ __launch_bounds__(256)
void prep_kernel(const float* __restrict__ W1, const float* __restrict__ W2,
                 const float* __restrict__ Wt, const float* __restrict__ Wa)
{
    int i = blockIdx.x * 256 + threadIdx.x;
    const int t0 = Dd * Hh;            // 16384
    const int t1 = Hh * Hh;            // 65536
    const int t2 = Hh * HO;            // 36864
    if (i < t0) {
        int k = i >> 8, o = i & 255;
        g_WT1[i] = W1[o * Dd + k];
    } else if (i < t0 + t1) {
        int j = i - t0;
        int k = j >> 8, o = j & 255;
        g_WT2[j] = W2[o * Hh + k];
    } else if (i < t0 + t1 + t2) {
        int j = i - t0 - t1;
        int k = j / HO, o = j % HO;
        g_WhT[j] = (o < Nn) ? Wt[o * Hh + k] : Wa[(o - Nn) * Hh + k];
    }
}

// ---------------------------------------------------------------------------
// Kernel 1: MLP. 128 blocks x 4 rows, 256 threads. thread = output column,
// weights read coalesced from transposed scratch, activations via smem bcast.
// ---------------------------------------------------------------------------
__global__ __launch_bounds__(256)
void mlp_kernel(const float* __restrict__ x,
                const float* __restrict__ b1, const float* __restrict__ b2,
                const float* __restrict__ bt, const float* __restrict__ ba)
{
    __shared__ float xs [RPB][Dd];
    __shared__ float h1s[RPB][Hh];
    __shared__ float h2s[RPB][Hh];

    const int tid = threadIdx.x;
    const int e0  = blockIdx.x * RPB;

    // RPB*Dd == 256: one element per thread, coalesced
    xs[tid >> 6][tid & 63] = x[e0 * Dd + tid];
    __syncthreads();

    // ---- layer 1 ----
    {
        float acc[RPB];
        float bias = b1[tid];
        #pragma unroll
        for (int r = 0; r < RPB; r++) acc[r] = bias;
        #pragma unroll 4
        for (int k = 0; k < Dd; k += 4) {
            float w0 = g_WT1[(k + 0) * Hh + tid];
            float w1 = g_WT1[(k + 1) * Hh + tid];
            float w2 = g_WT1[(k + 2) * Hh + tid];
            float w3 = g_WT1[(k + 3) * Hh + tid];
            #pragma unroll
            for (int r = 0; r < RPB; r++) {
                float4 v = *(const float4*)&xs[r][k];
                acc[r] += w0 * v.x + w1 * v.y + w2 * v.z + w3 * v.w;
            }
        }
        #pragma unroll
        for (int r = 0; r < RPB; r++) h1s[r][tid] = tanhf(acc[r]);
    }
    __syncthreads();

    // ---- layer 2 ----
    {
        float acc[RPB];
        float bias = b2[tid];
        #pragma unroll
        for (int r = 0; r < RPB; r++) acc[r] = bias;
        #pragma unroll 4
        for (int k = 0; k < Hh; k += 4) {
            float w0 = g_WT2[(k + 0) * Hh + tid];
            float w1 = g_WT2[(k + 1) * Hh + tid];
            float w2 = g_WT2[(k + 2) * Hh + tid];
            float w3 = g_WT2[(k + 3) * Hh + tid];
            #pragma unroll
            for (int r = 0; r < RPB; r++) {
                float4 v = *(const float4*)&h1s[r][k];
                acc[r] += w0 * v.x + w1 * v.y + w2 * v.z + w3 * v.w;
            }
        }
        #pragma unroll
        for (int r = 0; r < RPB; r++) h2s[r][tid] = tanhf(acc[r]);
    }
    __syncthreads();

    // ---- heads (144 outputs, threads 0..143) ----
    if (tid < HO) {
        float acc[RPB];
        float bias = (tid < Nn) ? bt[tid] : ba[tid - Nn];
        #pragma unroll
        for (int r = 0; r < RPB; r++) acc[r] = bias;
        #pragma unroll 4
        for (int k = 0; k < Hh; k += 4) {
            float w0 = g_WhT[(k + 0) * HO + tid];
            float w1 = g_WhT[(k + 1) * HO + tid];
            float w2 = g_WhT[(k + 2) * HO + tid];
            float w3 = g_WhT[(k + 3) * HO + tid];
            #pragma unroll
            for (int r = 0; r < RPB; r++) {
                float4 v = *(const float4*)&h2s[r][k];
                acc[r] += w0 * v.x + w1 * v.y + w2 * v.z + w3 * v.w;
            }
        }
        if (tid < Nn) {
            #pragma unroll
            for (int r = 0; r < RPB; r++) g_times[(e0 + r) * Nn + tid] = acc[r];
        } else {
            #pragma unroll
            for (int r = 0; r < RPB; r++) g_anchors[(e0 + r) * (Aa * Nn) + (tid - Nn)] = acc[r];
        }
    }
}

// ---------------------------------------------------------------------------
// Kernel 2: fused GP per environment e. 512 blocks, 256 threads.
//   warp 0: build K + Gauss-Jordan (syncwarp only);  warps 1-7: Ks + kssd.
//   cov depends only on t -> compute once, store 8x with streaming stores.
// ---------------------------------------------------------------------------
__global__ __launch_bounds__(256)
void gp_kernel(const float* __restrict__ tq_g,
               float* __restrict__ out_mu,
               float* __restrict__ out_cov)
{
    __shared__ float tq[Tt];
    __shared__ float kssd[Tt];               // Kss[i][j] == kssd[|i-j|]
    __shared__ float tt[Nn];
    __shared__ float ys[Aa][Nn];
    __shared__ float Aug[Nn][2 * Nn + 1];    // [K | I] -> [I | K^-1], pad 33
    __shared__ float St[Nn][Tt + 4];         // Ks transposed, pad 132
    __shared__ float U[Tt][Nn + 1];          // U = Ks @ K^-1, pad 17

    const int e    = blockIdx.x;
    const int tid  = threadIdx.x;
    const int wid  = tid >> 5;
    const int lane = tid & 31;

    if (tid < Tt) {
        tq[tid] = tq_g[tid];
        ys[tid >> 4][tid & 15] = g_anchors[e * (Aa * Nn) + tid];
    } else if (tid < Tt + Nn) {
        tt[tid - Tt] = g_times[e * Nn + (tid - Tt)];
    }
    __syncthreads();

    if (wid == 0) {
        // ---- build [K + sn2 I | I], then Gauss-Jordan with syncwarp only ----
        #pragma unroll
        for (int r = 0; r < 8; r++) {
            int idx = r * 32 + lane;
            int i = idx >> 4, j = idx & 15;
            float d = tt[i] - tt[j];
            float v = SF2 * __expf(NEG_HALF_INV_L2 * d * d);
            if (i == j) v += SN2;
            Aug[i][j] = v;
            Aug[i][Nn + j] = (i == j) ? 1.0f : 0.0f;
        }
        __syncwarp();
        for (int k = 0; k < Nn; k++) {
            float pinv = 1.0f / Aug[k][k];
            float rowk = Aug[k][lane] * pinv;
            Aug[k][lane] = rowk;
            __syncwarp();
            #pragma unroll
            for (int i = 0; i < Nn; i++) {
                if (i != k) {
                    float c = Aug[i][k];     // LDS precedes STS in the stream
                    Aug[i][lane] -= c * rowk;
                }
            }
            __syncwarp();
        }
    } else {
        // ---- warps 1..7: Ks transposed + kssd table ----
        for (int idx = tid - 32; idx < Tt * Nn; idx += 224) {
            int j = idx >> 4, n = idx & 15;
            float d = tq[j] - tt[n];
            St[n][j] = SF2 * __expf(NEG_HALF_INV_L2 * d * d);
        }
        if (tid >= 32 && tid < 32 + Tt) {
            int j = tid - 32;
            float d = tq[j] - tq[0];
            kssd[j] = SF2 * __expf(NEG_HALF_INV_L2 * d * d);
        }
    }
    __syncthreads();

    // U[i][n] = sum_m Ks[i][m] * Kinv[m][n]
    for (int idx = tid; idx < Tt * Nn; idx += 256) {
        int i = idx >> 4, n = idx & 15;
        float s = 0.0f;
        #pragma unroll
        for (int m = 0; m < Nn; m++) s += St[m][i] * Aug[m][Nn + n];
        U[i][n] = s;
    }
    __syncthreads();

    // mu[a][i] = dot16(U[i], y[a])
    for (int idx = tid; idx < Aa * Tt; idx += 256) {
        int a = idx >> 7, i = idx & 127;
        float s = 0.0f;
        #pragma unroll
        for (int n = 0; n < Nn; n++) s += U[i][n] * ys[a][n];
        out_mu[((size_t)e * Aa + a) * Tt + i] = s;
    }

    // cov[i][j] = kssd[|i-j|] - dot16(U[i], Ks[j]); streamed out 8x
    const int grp = wid;
    const int j0  = lane * 4;
    for (int step = 0; step < Tt / 8; step++) {
        int i = step * 8 + grp;
        float u[Nn];
        #pragma unroll
        for (int n = 0; n < Nn; n++) u[n] = U[i][n];   // broadcast LDS
        float a0 = 0.f, a1 = 0.f, a2 = 0.f, a3 = 0.f;
        #pragma unroll
        for (int n = 0; n < Nn; n++) {
            float4 s4 = *(const float4*)&St[n][j0];    // conflict-free LDS.128
            float un = u[n];
            a0 += un * s4.x; a1 += un * s4.y; a2 += un * s4.z; a3 += un * s4.w;
        }
        int d0 = i - j0;       d0 = d0 < 0 ? -d0 : d0;
        int d1 = i - (j0 + 1); d1 = d1 < 0 ? -d1 : d1;
        int d2 = i - (j0 + 2); d2 = d2 < 0 ? -d2 : d2;
        int d3 = i - (j0 + 3); d3 = d3 < 0 ? -d3 : d3;
        float4 v;
        v.x = kssd[d0] - a0;
        v.y = kssd[d1] - a1;
        v.z = kssd[d2] - a2;
        v.w = kssd[d3] - a3;
        size_t base = (((size_t)e * Aa) * Tt + i) * Tt + j0;
        #pragma unroll
        for (int a = 0; a < Aa; a++)
            __stcs((float4*)&out_cov[base + (size_t)a * Tt * Tt], v);  // streaming STG.128
    }
}

// ---------------------------------------------------------------------------
extern "C" void kernel_launch(void* const* d_in, const int* in_sizes, int n_in,
                              void* d_out, int out_size)
{
    const float* x  = (const float*)d_in[0];
    // d_in[1] = a, d_in[2] = da (unused by reference)
    const float* W1 = (const float*)d_in[3];
    const float* b1 = (const float*)d_in[4];
    const float* W2 = (const float*)d_in[5];
    const float* b2 = (const float*)d_in[6];
    const float* Wt = (const float*)d_in[7];
    const float* bt = (const float*)d_in[8];
    const float* Wa = (const float*)d_in[9];
    const float* ba = (const float*)d_in[10];
    const float* tq = (const float*)d_in[11];

    float* out     = (float*)d_out;
    float* out_mu  = out;                                   // E*A*T floats
    float* out_cov = out + (size_t)E_TOT * Aa * Tt;         // E*A*T*T floats

    const int prep_elems = Dd * Hh + Hh * Hh + Hh * HO;
    prep_kernel<<<(prep_elems + 255) / 256, 256>>>(W1, W2, Wt, Wa);
    mlp_kernel<<<E_TOT / RPB, 256>>>(x, b1, b2, bt, ba);
    gp_kernel<<<E_TOT, 256>>>(tq, out_mu, out_cov);
}